// round 6
// baseline (speedup 1.0000x reference)
#include <cuda_runtime.h>
#include <cuda_bf16.h>

// feature_maps: [1, 200, 304, 256] fp32 (NHWC) | proposals: [N,4] (x1,y1,x2,y2)
// image_shape: [2] int32 | output: [N, 7, 7, 256] fp32
#define HF   200
#define WF   304
#define CC   256
#define CROP 14
#define POOL 7

struct __align__(16) Axis {
    int   o0;   // clipped floor index * stride (elements)
    int   o1;   // clipped (floor+1) index * stride
    float l;    // interpolation fraction
    float v;    // validity (1.0f / 0.0f)
};

__device__ __forceinline__ float4 lerp4(float4 a, float4 b, float t) {
    float4 r;
    r.x = fmaf(b.x - a.x, t, a.x);
    r.y = fmaf(b.y - a.y, t, a.y);
    r.z = fmaf(b.z - a.z, t, a.z);
    r.w = fmaf(b.w - a.w, t, a.w);
    return r;
}

__device__ __forceinline__ float4 max4(float4 a, float4 b) {
    float4 r;
    r.x = fmaxf(a.x, b.x);
    r.y = fmaxf(a.y, b.y);
    r.z = fmaxf(a.z, b.z);
    r.w = fmaxf(a.w, b.w);
    return r;
}

__device__ __forceinline__ float4 scale4(float4 a, float s) {
    float4 r; r.x = a.x * s; r.y = a.y * s; r.z = a.z * s; r.w = a.w * s;
    return r;
}

__global__ __launch_bounds__(256, 4)
void roi_pool_kernel(const float* __restrict__ fm,
                     const float* __restrict__ props,
                     const int*   __restrict__ ishape,
                     float* __restrict__ out,
                     int N)
{
    __shared__ Axis sy[CROP];
    __shared__ Axis sx[CROP];

    const int n   = blockIdx.x;
    const int tx  = threadIdx.x;                    // 0..63: channel group (float4)
    const int ty  = threadIdx.y;                    // 0..3 : pooled-cell slice
    const int tid = ty * 64 + tx;

    // ---- Per-box axis parameters (28 threads, once per box) ----
    if (tid < 2 * CROP) {
        const float h = (float)ishape[0];
        const float w = (float)ishape[1];
        const float* p = props + (size_t)n * 4;
        const bool isY = (tid < CROP);
        const int  i   = isY ? tid : tid - CROP;
        const float c1 = isY ? (p[1] / h) : (p[0] / w);
        const float c2 = isY ? (p[3] / h) : (p[2] / w);
        const float D  = isY ? (float)(HF - 1) : (float)(WF - 1);
        const int   stride = isY ? (WF * CC) : CC;
        const float step = (c2 - c1) * D / (float)(CROP - 1);
        const float s    = fmaf((float)i, step, c1 * D);
        const float f    = floorf(s);
        int i0 = (int)f;
        i0 = max(0, min(i0, (int)D));
        const int i1 = min(i0 + 1, (int)D);
        Axis a;
        a.o0 = i0 * stride;
        a.o1 = i1 * stride;
        a.l  = s - f;
        a.v  = (s >= 0.0f && s <= D) ? 1.0f : 0.0f;
        if (isY) sy[i] = a; else sx[i] = a;
    }
    __syncthreads();

    const float* fmc = fm + tx * 4;   // fold channel offset into the base pointer

    // ---- Contiguous cell range per ty: [0,12) [12,24) [24,36) [36,49) ----
    // Consecutive cells share the same py row-pair for ~7 iterations and their
    // x-corner windows advance by only 2*step -> tighter L1 temporal reuse.
    const int cstart = (49 * ty) >> 2;
    const int cend   = (49 * (ty + 1)) >> 2;

    for (int cell = cstart; cell < cend; ++cell) {
        const int py = cell / POOL;
        const int px = cell - py * POOL;

        const Axis ax0 = sx[2 * px];
        const Axis ax1 = sx[2 * px + 1];

        float4 m = make_float4(-__FLT_MAX__, -__FLT_MAX__, -__FLT_MAX__, -__FLT_MAX__);

        #pragma unroll
        for (int dy = 0; dy < 2; ++dy) {
            const Axis ay = sy[2 * py + dy];
            const float* r0 = fmc + ay.o0;
            const float* r1 = fmc + ay.o1;

            // front-batch all 8 loads for this y-sample before any math
            const float4 a00 = *(const float4*)(r0 + ax0.o0);
            const float4 a01 = *(const float4*)(r0 + ax0.o1);
            const float4 a10 = *(const float4*)(r1 + ax0.o0);
            const float4 a11 = *(const float4*)(r1 + ax0.o1);
            const float4 b00 = *(const float4*)(r0 + ax1.o0);
            const float4 b01 = *(const float4*)(r0 + ax1.o1);
            const float4 b10 = *(const float4*)(r1 + ax1.o0);
            const float4 b11 = *(const float4*)(r1 + ax1.o1);

            const float ly = ay.l;
            const float va = ay.v * ax0.v;
            const float vb = ay.v * ax1.v;

            // sample (dy, dx=0)
            float4 ta = lerp4(a00, a01, ax0.l);
            float4 ba = lerp4(a10, a11, ax0.l);
            float4 sa = scale4(lerp4(ta, ba, ly), va);
            m = max4(m, sa);

            // sample (dy, dx=1)
            float4 tb = lerp4(b00, b01, ax1.l);
            float4 bb = lerp4(b10, b11, ax1.l);
            float4 sb = scale4(lerp4(tb, bb, ly), vb);
            m = max4(m, sb);
        }

        float* o = out + (((size_t)n * (POOL * POOL)) + cell) * CC + tx * 4;
        __stcs((float4*)o, m);   // streaming store: keep the feature map in L2
    }
}

extern "C" void kernel_launch(void* const* d_in, const int* in_sizes, int n_in,
                              void* d_out, int out_size) {
    const float* fm     = (const float*)d_in[0];
    const float* props  = (const float*)d_in[1];
    const int*   ishape = (const int*)  d_in[2];
    float*       out    = (float*)d_out;

    const int N = in_sizes[1] / 4;   // proposals: [N, 4]

    dim3 block(64, 4, 1);
    dim3 grid(N, 1, 1);
    roi_pool_kernel<<<grid, block>>>(fm, props, ishape, out, N);
}

// round 7
// speedup vs baseline: 1.1144x; 1.1144x over previous
#include <cuda_runtime.h>
#include <cuda_bf16.h>

// feature_maps: [1, 200, 304, 256] fp32 (NHWC) | proposals: [N,4] (x1,y1,x2,y2)
// image_shape: [2] int32 | output: [N, 7, 7, 256] fp32
#define HF   200
#define WF   304
#define CC   256
#define CROP 14
#define POOL 7

struct __align__(16) Axis {
    int   o0;   // clipped floor index * stride (elements)
    int   o1;   // clipped (floor+1) index * stride
    float l;    // interpolation fraction
    float v;    // validity (1.0f / 0.0f)
};

__device__ __forceinline__ float4 lerp4(float4 a, float4 b, float t) {
    float4 r;
    r.x = fmaf(b.x - a.x, t, a.x);
    r.y = fmaf(b.y - a.y, t, a.y);
    r.z = fmaf(b.z - a.z, t, a.z);
    r.w = fmaf(b.w - a.w, t, a.w);
    return r;
}

__device__ __forceinline__ float4 max4(float4 a, float4 b) {
    float4 r;
    r.x = fmaxf(a.x, b.x);
    r.y = fmaxf(a.y, b.y);
    r.z = fmaxf(a.z, b.z);
    r.w = fmaxf(a.w, b.w);
    return r;
}

__device__ __forceinline__ float4 scale4(float4 a, float s) {
    float4 r; r.x = a.x * s; r.y = a.y * s; r.z = a.z * s; r.w = a.w * s;
    return r;
}

// 13 groups of 4 adjacent cells (last group = cell 48 only), split over 4 CTAs.
// Group boundaries per blockIdx.y: [0,3) [3,6) [6,9) [9,13)
__global__ __launch_bounds__(256, 4)
void roi_pool_kernel(const float* __restrict__ fm,
                     const float* __restrict__ props,
                     const int*   __restrict__ ishape,
                     float* __restrict__ out,
                     int N)
{
    __shared__ Axis sy[CROP];
    __shared__ Axis sx[CROP];

    const int n   = blockIdx.x;
    const int by  = blockIdx.y;                     // 0..3: cell-group quarter
    const int tx  = threadIdx.x;                    // 0..63: channel group (float4)
    const int ty  = threadIdx.y;                    // 0..3 : cell within group
    const int tid = ty * 64 + tx;

    // ---- Per-box axis parameters (28 threads, once per CTA) ----
    if (tid < 2 * CROP) {
        const float h = (float)ishape[0];
        const float w = (float)ishape[1];
        const float* p = props + (size_t)n * 4;
        const bool isY = (tid < CROP);
        const int  i   = isY ? tid : tid - CROP;
        const float c1 = isY ? (p[1] / h) : (p[0] / w);
        const float c2 = isY ? (p[3] / h) : (p[2] / w);
        const float D  = isY ? (float)(HF - 1) : (float)(WF - 1);
        const int   stride = isY ? (WF * CC) : CC;
        const float step = (c2 - c1) * D / (float)(CROP - 1);
        const float s    = fmaf((float)i, step, c1 * D);
        const float f    = floorf(s);
        int i0 = (int)f;
        i0 = max(0, min(i0, (int)D));
        const int i1 = min(i0 + 1, (int)D);
        Axis a;
        a.o0 = i0 * stride;
        a.o1 = i1 * stride;
        a.l  = s - f;
        a.v  = (s >= 0.0f && s <= D) ? 1.0f : 0.0f;
        if (isY) sy[i] = a; else sx[i] = a;
    }
    __syncthreads();

    const float* fmc = fm + tx * 4;   // fold channel offset into the base pointer

    const int gstart = (13 * by) >> 2;        // 0,3,6,9
    const int gend   = (13 * (by + 1)) >> 2;  // 3,6,9,13

    for (int g = gstart; g < gend; ++g) {
        const int cell = 4 * g + ty;          // 4 adjacent cells per iteration (cross-warp reuse)
        if (cell >= POOL * POOL) break;

        const int py = cell / POOL;
        const int px = cell - py * POOL;

        const Axis ax0 = sx[2 * px];
        const Axis ax1 = sx[2 * px + 1];

        float4 m = make_float4(-__FLT_MAX__, -__FLT_MAX__, -__FLT_MAX__, -__FLT_MAX__);

        #pragma unroll
        for (int dy = 0; dy < 2; ++dy) {
            const Axis ay = sy[2 * py + dy];
            const float* r0 = fmc + ay.o0;
            const float* r1 = fmc + ay.o1;

            // front-batch all 8 loads for this y-sample before any math
            const float4 a00 = *(const float4*)(r0 + ax0.o0);
            const float4 a01 = *(const float4*)(r0 + ax0.o1);
            const float4 a10 = *(const float4*)(r1 + ax0.o0);
            const float4 a11 = *(const float4*)(r1 + ax0.o1);
            const float4 b00 = *(const float4*)(r0 + ax1.o0);
            const float4 b01 = *(const float4*)(r0 + ax1.o1);
            const float4 b10 = *(const float4*)(r1 + ax1.o0);
            const float4 b11 = *(const float4*)(r1 + ax1.o1);

            const float ly = ay.l;
            const float va = ay.v * ax0.v;
            const float vb = ay.v * ax1.v;

            float4 ta = lerp4(a00, a01, ax0.l);
            float4 ba = lerp4(a10, a11, ax0.l);
            float4 sa = scale4(lerp4(ta, ba, ly), va);
            m = max4(m, sa);

            float4 tb = lerp4(b00, b01, ax1.l);
            float4 bb = lerp4(b10, b11, ax1.l);
            float4 sb = scale4(lerp4(tb, bb, ly), vb);
            m = max4(m, sb);
        }

        float* o = out + (((size_t)n * (POOL * POOL)) + cell) * CC + tx * 4;
        __stcs((float4*)o, m);   // streaming store: keep the feature map in L2
    }
}

extern "C" void kernel_launch(void* const* d_in, const int* in_sizes, int n_in,
                              void* d_out, int out_size) {
    const float* fm     = (const float*)d_in[0];
    const float* props  = (const float*)d_in[1];
    const int*   ishape = (const int*)  d_in[2];
    float*       out    = (float*)d_out;

    const int N = in_sizes[1] / 4;   // proposals: [N, 4]

    dim3 block(64, 4, 1);
    dim3 grid(N, 4, 1);
    roi_pool_kernel<<<grid, block>>>(fm, props, ishape, out, N);
}